// round 12
// baseline (speedup 1.0000x reference)
#include <cuda_runtime.h>
#include <cuda_fp16.h>
#include <cstdint>
#include <cstddef>

// ---------------- problem constants ----------------
#define B_WIN 4096
#define N_TOK 49
#define CH    512
#define NH    16
#define HD    32
#define M_ROWS (B_WIN * N_TOK)      // 200704
#define QKV_N  (3 * CH)             // 1536

// ---------------- scratch (static device globals; alloc-free rule) ----------
__device__ __half g_xh   [(long long)M_ROWS * CH];            // x in fp16
__device__ __half g_q    [(long long)B_WIN * NH * N_TOK * HD];// [B,H,N,hd] fp16
__device__ __half g_k    [(long long)B_WIN * NH * N_TOK * HD];
__device__ __half g_v    [(long long)B_WIN * NH * N_TOK * HD];
__device__ __half g_attn [(long long)M_ROWS * CH];            // [B,N,C] fp16
__device__ __half g_wqkvh[(long long)QKV_N * CH];             // [N=1536,K=512] K-major fp16
__device__ __half g_wprojh[(long long)CH * CH];               // [N=512, K=512] K-major fp16

// ---------------- PTX helpers ----------------
__device__ __forceinline__ void mma_f16(float c[4], const uint32_t a[4], const uint32_t b[2]) {
    asm volatile(
        "mma.sync.aligned.m16n8k16.row.col.f32.f16.f16.f32 "
        "{%0,%1,%2,%3}, {%4,%5,%6,%7}, {%8,%9}, {%0,%1,%2,%3};\n"
        : "+f"(c[0]), "+f"(c[1]), "+f"(c[2]), "+f"(c[3])
        : "r"(a[0]), "r"(a[1]), "r"(a[2]), "r"(a[3]),
          "r"(b[0]), "r"(b[1]));
}
__device__ __forceinline__ void ldm_x4(uint32_t& r0, uint32_t& r1, uint32_t& r2, uint32_t& r3,
                                       uint32_t saddr) {
    asm volatile("ldmatrix.sync.aligned.m8n8.x4.shared.b16 {%0,%1,%2,%3}, [%4];"
                 : "=r"(r0), "=r"(r1), "=r"(r2), "=r"(r3) : "r"(saddr));
}
__device__ __forceinline__ void cp_async16(void* smem, const void* gmem) {
    uint32_t s = (uint32_t)__cvta_generic_to_shared(smem);
    asm volatile("cp.async.cg.shared.global [%0], [%1], 16;\n" :: "r"(s), "l"(gmem));
}
__device__ __forceinline__ void cp_commit() { asm volatile("cp.async.commit_group;\n" ::: "memory"); }
__device__ __forceinline__ void cp_wait0()  { asm volatile("cp.async.wait_group 0;\n" ::: "memory"); }

// fast exp on the FFMA pipe. Valid for x <= 0 (clamped at -80).
__device__ __forceinline__ float fast_exp(float x) {
    x = fmaxf(x, -80.0f);
    float y = x * 1.4426950408889634f;
    float t = y + 12582912.0f;                 // 1.5*2^23: round-to-nearest
    int   n = __float_as_int(t) - 0x4B400000;  // integer part
    float f = y - (t - 12582912.0f);           // f in [-0.5, 0.5]
    float p = 1.33335581e-3f;
    p = fmaf(p, f, 9.61812911e-3f);
    p = fmaf(p, f, 5.55041087e-2f);
    p = fmaf(p, f, 2.40226507e-1f);
    p = fmaf(p, f, 6.93147180e-1f);
    p = fmaf(p, f, 1.0f);
    return __int_as_float(__float_as_int(p) + (n << 23));
}

// ---------------- fp16 GEMM: BK=64, 2-stage ring, ONE sync/iter ------------
// 128x128 tile, BK=64 (4 x k16), 256 threads, 8 warps (2x4), warp tile 64x32.
#define AS_H 72                      // 64 + 8 pad (144B rows: conflict-free ldm)
#define KT_CNT (CH / 64)             // 8
#define STAGE_H (128 * AS_H)         // halves per operand per stage
#define GEMM_DSM (2 * 2 * STAGE_H * 2)   // 73728 bytes

template<int EPI>
__global__ __launch_bounds__(256, 2)
void gemm_h_kernel(const float* __restrict__ bias, float* __restrict__ Cout, int N)
{
    extern __shared__ __half dsm[];   // [2 stages][As 128*72 | Bs 128*72]

    const __half* A  = (EPI == 0) ? g_xh   : g_attn;
    const __half* Bt = (EPI == 0) ? g_wqkvh : g_wprojh;

    const int tid  = threadIdx.x;
    const int lane = tid & 31;
    const int warp = tid >> 5;
    const int wm   = warp >> 2;
    const int wn   = warp & 3;
    const int bm   = blockIdx.y * 128;
    const int bn   = blockIdx.x * 128;
    const int grp  = lane >> 2;
    const int tig  = lane & 3;

    const int lg  = lane >> 3;
    const int lr  = lane & 7;
    const int a_row = (lg & 1) * 8 + lr;
    const int a_k   = (lg >> 1) * 8;
    const int b_row = (lg >> 1) * 8 + lr;
    const int b_k   = (lg & 1) * 8;

    const uint32_t sm_base = (uint32_t)__cvta_generic_to_shared(dsm);

    float acc[4][4][4];
    #pragma unroll
    for (int mt = 0; mt < 4; mt++)
        #pragma unroll
        for (int nt = 0; nt < 4; nt++)
            #pragma unroll
            for (int r = 0; r < 4; r++) acc[mt][nt][r] = 0.0f;

    auto load_stage = [&](int kt, int s) {
        __half* As = dsm + s * 2 * STAGE_H;
        __half* Bs = As + STAGE_H;
        #pragma unroll
        for (int i = 0; i < 4; i++) {
            int idx = tid + i * 256;            // 0..1023
            int row = idx >> 3, seg = idx & 7;
            cp_async16(&As[row * AS_H + seg * 8],
                       A + (size_t)(bm + row) * CH + kt * 64 + seg * 8);
        }
        #pragma unroll
        for (int i = 0; i < 4; i++) {
            int idx = tid + i * 256;
            int row = idx >> 3, seg = idx & 7;
            cp_async16(&Bs[row * AS_H + seg * 8],
                       Bt + (size_t)(bn + row) * CH + kt * 64 + seg * 8);
        }
        cp_commit();
    };

    load_stage(0, 0);

    #pragma unroll 1
    for (int kt = 0; kt < KT_CNT; kt++) {
        cp_wait0();                            // stage kt loaded
        __syncthreads();                       // + compute kt-1 done everywhere
        if (kt + 1 < KT_CNT) load_stage(kt + 1, (kt + 1) & 1);

        const int s = kt & 1;
        const uint32_t as0 = sm_base + (uint32_t)(s * 2 * STAGE_H * 2);
        const uint32_t bs0 = as0 + STAGE_H * 2;
        #pragma unroll
        for (int ks = 0; ks < 4; ks++) {
            const int k0 = ks * 16;
            uint32_t af[4][4], bf[4][2];
            #pragma unroll
            for (int mt = 0; mt < 4; mt++) {
                uint32_t addr = as0 +
                    (uint32_t)(((wm * 64 + mt * 16 + a_row) * AS_H + k0 + a_k) * 2);
                ldm_x4(af[mt][0], af[mt][1], af[mt][2], af[mt][3], addr);
            }
            #pragma unroll
            for (int p = 0; p < 2; p++) {
                uint32_t addr = bs0 +
                    (uint32_t)(((wn * 32 + p * 16 + b_row) * AS_H + k0 + b_k) * 2);
                ldm_x4(bf[2 * p][0], bf[2 * p][1], bf[2 * p + 1][0], bf[2 * p + 1][1], addr);
            }
            #pragma unroll
            for (int mt = 0; mt < 4; mt++)
                #pragma unroll
                for (int nt = 0; nt < 4; nt++)
                    mma_f16(acc[mt][nt], af[mt], bf[nt]);
        }
    }

    // -------- epilogue --------
    #pragma unroll
    for (int mt = 0; mt < 4; mt++) {
        #pragma unroll
        for (int rr = 0; rr < 2; rr++) {
            int row = bm + wm * 64 + mt * 16 + grp + rr * 8;
            int b   = row / N_TOK;
            int n   = row - b * N_TOK;
            #pragma unroll
            for (int nt = 0; nt < 4; nt++) {
                int col0 = bn + wn * 32 + nt * 8 + (tig << 1);
                float v0 = acc[mt][nt][rr * 2 + 0] + bias[col0];
                float v1 = acc[mt][nt][rr * 2 + 1] + bias[col0 + 1];
                if (EPI == 0) {
                    int which = col0 >> 9;
                    int h     = (col0 >> 5) & 15;
                    int d     = col0 & 31;
                    __half* dst = (which == 0) ? g_q : ((which == 1) ? g_k : g_v);
                    dst += (((size_t)b * NH + h) * N_TOK + n) * HD + d;
                    *(__half2*)dst = __floats2half2_rn(v0, v1);
                } else {
                    *(float2*)&Cout[(size_t)row * N + col0] = make_float2(v0, v1);
                }
            }
        }
    }
}

// ---------------- converters ----------------
__global__ void cvt_x_kernel(const float4* __restrict__ src)
{
    size_t i = (size_t)blockIdx.x * blockDim.x + threadIdx.x;
    float4 v = src[i];
    __half2 a = __floats2half2_rn(v.x, v.y);
    __half2 b = __floats2half2_rn(v.z, v.w);
    uint2 o = make_uint2(*(uint32_t*)&a, *(uint32_t*)&b);
    ((uint2*)g_xh)[i] = o;
}

template<int W>
__global__ void transpose_cvt_kernel(const float* __restrict__ src, int K, int N)
{
    __half* dst = (W == 0) ? g_wqkvh : g_wprojh;
    __shared__ float t[32][33];
    int nx = blockIdx.x * 32, kx = blockIdx.y * 32;
    #pragma unroll
    for (int i = 0; i < 4; i++)
        t[threadIdx.y + 8 * i][threadIdx.x] =
            src[(size_t)(kx + threadIdx.y + 8 * i) * N + nx + threadIdx.x];
    __syncthreads();
    #pragma unroll
    for (int i = 0; i < 4; i++)
        dst[(size_t)(nx + threadIdx.y + 8 * i) * K + kx + threadIdx.x] =
            __float2half_rn(t[threadIdx.x][threadIdx.y + 8 * i]);
}

// ---------------- tensor-core attention, register softmax, warp-local ------
// 128 threads (4 warps), one (window, head) per block.
// __launch_bounds__(128, 4): 128-reg budget -- the live set (S frags + softmax
// temps + O frags) needs ~110 regs; the old (128,6) bound capped at 85 and
// forced local-memory spills in the hot loops.
#define AT_OFF_K   5120
#define AT_OFF_VT  10240
#define AT_OFF_P   14848
#define AT_OFF_BS  24064
#define AT_SMEM    24744
#define V_ST 72

__global__ __launch_bounds__(128, 4)
void attn_mma_kernel(const float* __restrict__ bias_table)
{
    const int h  = blockIdx.x;
    const int wi = blockIdx.y;
    const int t  = threadIdx.x;
    const int warp = t >> 5;
    const int lane = t & 31;

    __shared__ __align__(16) char sm_raw[AT_SMEM];
    __half* hQ  = (__half*)(sm_raw);
    __half* hK  = (__half*)(sm_raw + AT_OFF_K);
    __half* hVt = (__half*)(sm_raw + AT_OFF_VT);
    __half* hP  = (__half*)(sm_raw + AT_OFF_P);
    float*  fBs = (float*)(sm_raw + AT_OFF_BS);

    for (int i = t; i < 169; i += 128) fBs[i] = bias_table[i * NH + h];

    const size_t base = ((size_t)wi * NH + h) * (N_TOK * HD);
    const uint4* gq = (const uint4*)(g_q + base);
    const uint4* gk = (const uint4*)(g_k + base);
    const __half* gv = g_v + base;

    for (int f = t; f < 196; f += 128) {       // Q,K: 49 rows x 32 halves
        int n = f >> 2, sg = f & 3;
        *(uint4*)&hQ[n * 40 + sg * 8] = gq[f];
        *(uint4*)&hK[n * 40 + sg * 8] = gk[f];
    }
    for (int idx = t; idx < N_TOK * HD; idx += 128) {   // Vt[d][m] = V[m][d]
        int n = idx >> 5, d = idx & 31;
        hVt[d * V_ST + n] = gv[idx];
    }
    for (int idx = t; idx < 32 * 15; idx += 128) {      // zero Vt pad cols
        int d = idx / 15, m = 49 + idx % 15;
        hVt[d * V_ST + m] = __ushort_as_half((unsigned short)0);
    }
    __syncthreads();   // the ONLY block barrier

    // ---- S = Q K^T : warp handles rows 16*warp..+15 ----
    const int lg = lane >> 3, lr = lane & 7;
    const int a_row = (lg & 1) * 8 + lr;
    const int a_k   = (lg >> 1) * 8;
    const int b_row = (lg >> 1) * 8 + lr;
    const int b_k   = (lg & 1) * 8;
    const uint32_t qb = (uint32_t)__cvta_generic_to_shared(hQ);
    const uint32_t kb = (uint32_t)__cvta_generic_to_shared(hK);

    float sc[7][4];
    #pragma unroll
    for (int nt = 0; nt < 7; nt++)
        #pragma unroll
        for (int r = 0; r < 4; r++) sc[nt][r] = 0.f;

    #pragma unroll
    for (int ks = 0; ks < 2; ks++) {
        const int k0 = ks * 16;
        uint32_t af[4], bf[8][2];
        ldm_x4(af[0], af[1], af[2], af[3],
               qb + (uint32_t)(((16 * warp + a_row) * 40 + k0 + a_k) * 2));
        #pragma unroll
        for (int p = 0; p < 4; p++)
            ldm_x4(bf[2 * p][0], bf[2 * p][1], bf[2 * p + 1][0], bf[2 * p + 1][1],
                   kb + (uint32_t)(((p * 16 + b_row) * 40 + k0 + b_k) * 2));
        #pragma unroll
        for (int nt = 0; nt < 7; nt++)
            mma_f16(sc[nt], af, bf[nt]);
    }

    // ---- register softmax (quad = one row; shfl over tig lanes) ----
    const int grp = lane >> 2, tig = lane & 3;
    const float scale = 0.04419417382415922f;   // 512^-0.5
    float inv[2];
    #pragma unroll
    for (int rr = 0; rr < 2; rr++) {
        int r  = 16 * warp + grp + 8 * rr;
        int rc = min(r, 48);                    // clamp garbage rows: bounded bias idx
        int rd = (rc * 9363) >> 16;             // rc/7
        int rm = rc - rd * 7;
        float sv[7][2];
        float mx = -1e30f;
        #pragma unroll
        for (int nt = 0; nt < 7; nt++) {
            #pragma unroll
            for (int cc = 0; cc < 2; cc++) {
                int m = nt * 8 + 2 * tig + cc;
                float v = -1e30f;
                if (m < 49) {
                    int md = (m * 9363) >> 16;
                    int mm = m - md * 7;
                    v = sc[nt][rr * 2 + cc] * scale
                      + fBs[(rd - md + 6) * 13 + (rm - mm + 6)];
                }
                sv[nt][cc] = v;
                mx = fmaxf(mx, v);
            }
        }
        mx = fmaxf(mx, __shfl_xor_sync(0xffffffffu, mx, 1));
        mx = fmaxf(mx, __shfl_xor_sync(0xffffffffu, mx, 2));
        float sum = 0.f;
        #pragma unroll
        for (int nt = 0; nt < 7; nt++) {
            float e0 = fast_exp(sv[nt][0] - mx);
            float e1 = fast_exp(sv[nt][1] - mx);
            sum += e0 + e1;
            *(__half2*)&hP[r * V_ST + nt * 8 + 2 * tig] = __floats2half2_rn(e0, e1);
        }
        sum += __shfl_xor_sync(0xffffffffu, sum, 1);
        sum += __shfl_xor_sync(0xffffffffu, sum, 2);
        inv[rr] = 1.f / sum;
    }
    // zero this warp's hP pad cols 56..63 (rows 16*warp..+15)
    {
        int r = 16 * warp + (lane >> 1);
        int c = 56 + (lane & 1) * 4;
        *(uint2*)&hP[r * V_ST + c] = make_uint2(0u, 0u);
    }
    __syncwarp();      // hP rows for this warp visible to its own ldmatrix

    // ---- O = P V : warp rows 16*warp.. (A = its OWN hP rows), cols 0..31 ----
    {
        const uint32_t pb = (uint32_t)__cvta_generic_to_shared(hP);
        const uint32_t vb = (uint32_t)__cvta_generic_to_shared(hVt);
        float oc[4][4];
        #pragma unroll
        for (int nt = 0; nt < 4; nt++)
            #pragma unroll
            for (int r = 0; r < 4; r++) oc[nt][r] = 0.f;

        #pragma unroll
        for (int ks = 0; ks < 4; ks++) {
            const int k0 = ks * 16;
            uint32_t af[4], bf[4][2];
            ldm_x4(af[0], af[1], af[2], af[3],
                   pb + (uint32_t)(((16 * warp + a_row) * V_ST + k0 + a_k) * 2));
            #pragma unroll
            for (int p = 0; p < 2; p++)
                ldm_x4(bf[2 * p][0], bf[2 * p][1], bf[2 * p + 1][0], bf[2 * p + 1][1],
                       vb + (uint32_t)(((p * 16 + b_row) * V_ST + k0 + b_k) * 2));
            #pragma unroll
            for (int nt = 0; nt < 4; nt++)
                mma_f16(oc[nt], af, bf[nt]);
        }

        #pragma unroll
        for (int rr = 0; rr < 2; rr++) {
            int r = 16 * warp + grp + 8 * rr;
            if (r < 49) {
                size_t rowoff = ((size_t)wi * N_TOK + r) * CH + h * HD;
                #pragma unroll
                for (int nt = 0; nt < 4; nt++) {
                    int d = nt * 8 + 2 * tig;
                    __half2 o = __floats2half2_rn(oc[nt][rr * 2 + 0] * inv[rr],
                                                  oc[nt][rr * 2 + 1] * inv[rr]);
                    *(__half2*)(g_attn + rowoff + d) = o;
                }
            }
        }
    }
}

// ---------------- launch ----------------
extern "C" void kernel_launch(void* const* d_in, const int* in_sizes, int n_in,
                              void* d_out, int out_size)
{
    const float* x          = (const float*)d_in[0];
    const float* w_qkv      = (const float*)d_in[1];
    const float* b_qkv      = (const float*)d_in[2];
    const float* w_proj     = (const float*)d_in[3];
    const float* b_proj     = (const float*)d_in[4];
    const float* bias_table = (const float*)d_in[5];
    float* out = (float*)d_out;

    cudaFuncSetAttribute(gemm_h_kernel<0>, cudaFuncAttributeMaxDynamicSharedMemorySize, GEMM_DSM);
    cudaFuncSetAttribute(gemm_h_kernel<1>, cudaFuncAttributeMaxDynamicSharedMemorySize, GEMM_DSM);

    cvt_x_kernel<<<(M_ROWS * CH / 4) / 256, 256>>>((const float4*)x);
    transpose_cvt_kernel<0><<<dim3(QKV_N / 32, CH / 32), dim3(32, 8)>>>(w_qkv, CH, QKV_N);
    transpose_cvt_kernel<1><<<dim3(CH / 32,    CH / 32), dim3(32, 8)>>>(w_proj, CH, CH);

    gemm_h_kernel<0><<<dim3(QKV_N / 128, M_ROWS / 128), 256, GEMM_DSM>>>(b_qkv, nullptr, QKV_N);

    attn_mma_kernel<<<dim3(NH, B_WIN), 128>>>(bias_table);

    gemm_h_kernel<1><<<dim3(CH / 128, M_ROWS / 128), 256, GEMM_DSM>>>(b_proj, out, CH);
}

// round 13
// speedup vs baseline: 1.2989x; 1.2989x over previous
#include <cuda_runtime.h>
#include <cuda_fp16.h>
#include <cstdint>
#include <cstddef>

// ---------------- problem constants ----------------
#define B_WIN 4096
#define N_TOK 49
#define CH    512
#define NH    16
#define HD    32
#define M_ROWS (B_WIN * N_TOK)      // 200704
#define QKV_N  (3 * CH)             // 1536

// ---------------- scratch (static device globals; alloc-free rule) ----------
__device__ __half g_xh   [(long long)M_ROWS * CH];            // x in fp16
__device__ __half g_q    [(long long)B_WIN * NH * N_TOK * HD];// [B,H,N,hd] fp16
__device__ __half g_k    [(long long)B_WIN * NH * N_TOK * HD];
__device__ __half g_v    [(long long)B_WIN * NH * N_TOK * HD];
__device__ __half g_attn [(long long)M_ROWS * CH];            // [B,N,C] fp16
__device__ __half g_wqkvh[(long long)QKV_N * CH];             // [N=1536,K=512] K-major fp16
__device__ __half g_wprojh[(long long)CH * CH];               // [N=512, K=512] K-major fp16

// ---------------- PTX helpers ----------------
__device__ __forceinline__ void mma_f16(float c[4], const uint32_t a[4], const uint32_t b[2]) {
    asm volatile(
        "mma.sync.aligned.m16n8k16.row.col.f32.f16.f16.f32 "
        "{%0,%1,%2,%3}, {%4,%5,%6,%7}, {%8,%9}, {%0,%1,%2,%3};\n"
        : "+f"(c[0]), "+f"(c[1]), "+f"(c[2]), "+f"(c[3])
        : "r"(a[0]), "r"(a[1]), "r"(a[2]), "r"(a[3]),
          "r"(b[0]), "r"(b[1]));
}
__device__ __forceinline__ void ldm_x4(uint32_t& r0, uint32_t& r1, uint32_t& r2, uint32_t& r3,
                                       uint32_t saddr) {
    asm volatile("ldmatrix.sync.aligned.m8n8.x4.shared.b16 {%0,%1,%2,%3}, [%4];"
                 : "=r"(r0), "=r"(r1), "=r"(r2), "=r"(r3) : "r"(saddr));
}
__device__ __forceinline__ void ldm_x4_t(uint32_t& r0, uint32_t& r1, uint32_t& r2, uint32_t& r3,
                                         uint32_t saddr) {
    asm volatile("ldmatrix.sync.aligned.m8n8.x4.trans.shared.b16 {%0,%1,%2,%3}, [%4];"
                 : "=r"(r0), "=r"(r1), "=r"(r2), "=r"(r3) : "r"(saddr));
}
__device__ __forceinline__ void cp_async16(void* smem, const void* gmem) {
    uint32_t s = (uint32_t)__cvta_generic_to_shared(smem);
    asm volatile("cp.async.cg.shared.global [%0], [%1], 16;\n" :: "r"(s), "l"(gmem));
}
__device__ __forceinline__ void cp_async16_u(uint32_t saddr, const void* gmem) {
    asm volatile("cp.async.cg.shared.global [%0], [%1], 16;\n" :: "r"(saddr), "l"(gmem));
}
__device__ __forceinline__ void cp_commit() { asm volatile("cp.async.commit_group;\n" ::: "memory"); }
__device__ __forceinline__ void cp_wait0()  { asm volatile("cp.async.wait_group 0;\n" ::: "memory"); }

// fast exp on the FFMA pipe. Valid for x <= 0 (clamped at -80).
__device__ __forceinline__ float fast_exp(float x) {
    x = fmaxf(x, -80.0f);
    float y = x * 1.4426950408889634f;
    float t = y + 12582912.0f;                 // 1.5*2^23: round-to-nearest
    int   n = __float_as_int(t) - 0x4B400000;  // integer part
    float f = y - (t - 12582912.0f);           // f in [-0.5, 0.5]
    float p = 1.33335581e-3f;
    p = fmaf(p, f, 9.61812911e-3f);
    p = fmaf(p, f, 5.55041087e-2f);
    p = fmaf(p, f, 2.40226507e-1f);
    p = fmaf(p, f, 6.93147180e-1f);
    p = fmaf(p, f, 1.0f);
    return __int_as_float(__float_as_int(p) + (n << 23));
}

// ---------------- fp16 GEMM: BK=64, 2-stage ring, ONE sync/iter ------------
#define AS_H 72
#define KT_CNT (CH / 64)
#define STAGE_H (128 * AS_H)
#define GEMM_DSM (2 * 2 * STAGE_H * 2)   // 73728 bytes

template<int EPI>
__global__ __launch_bounds__(256, 2)
void gemm_h_kernel(const float* __restrict__ bias, float* __restrict__ Cout, int N)
{
    extern __shared__ __half dsm[];

    const __half* A  = (EPI == 0) ? g_xh   : g_attn;
    const __half* Bt = (EPI == 0) ? g_wqkvh : g_wprojh;

    const int tid  = threadIdx.x;
    const int lane = tid & 31;
    const int warp = tid >> 5;
    const int wm   = warp >> 2;
    const int wn   = warp & 3;
    const int bm   = blockIdx.y * 128;
    const int bn   = blockIdx.x * 128;
    const int grp  = lane >> 2;
    const int tig  = lane & 3;

    const int lg  = lane >> 3;
    const int lr  = lane & 7;
    const int a_row = (lg & 1) * 8 + lr;
    const int a_k   = (lg >> 1) * 8;
    const int b_row = (lg >> 1) * 8 + lr;
    const int b_k   = (lg & 1) * 8;

    const uint32_t sm_base = (uint32_t)__cvta_generic_to_shared(dsm);

    float acc[4][4][4];
    #pragma unroll
    for (int mt = 0; mt < 4; mt++)
        #pragma unroll
        for (int nt = 0; nt < 4; nt++)
            #pragma unroll
            for (int r = 0; r < 4; r++) acc[mt][nt][r] = 0.0f;

    auto load_stage = [&](int kt, int s) {
        __half* As = dsm + s * 2 * STAGE_H;
        __half* Bs = As + STAGE_H;
        #pragma unroll
        for (int i = 0; i < 4; i++) {
            int idx = tid + i * 256;
            int row = idx >> 3, seg = idx & 7;
            cp_async16(&As[row * AS_H + seg * 8],
                       A + (size_t)(bm + row) * CH + kt * 64 + seg * 8);
        }
        #pragma unroll
        for (int i = 0; i < 4; i++) {
            int idx = tid + i * 256;
            int row = idx >> 3, seg = idx & 7;
            cp_async16(&Bs[row * AS_H + seg * 8],
                       Bt + (size_t)(bn + row) * CH + kt * 64 + seg * 8);
        }
        cp_commit();
    };

    load_stage(0, 0);

    #pragma unroll 1
    for (int kt = 0; kt < KT_CNT; kt++) {
        cp_wait0();
        __syncthreads();
        if (kt + 1 < KT_CNT) load_stage(kt + 1, (kt + 1) & 1);

        const int s = kt & 1;
        const uint32_t as0 = sm_base + (uint32_t)(s * 2 * STAGE_H * 2);
        const uint32_t bs0 = as0 + STAGE_H * 2;
        #pragma unroll
        for (int ks = 0; ks < 4; ks++) {
            const int k0 = ks * 16;
            uint32_t af[4][4], bf[4][2];
            #pragma unroll
            for (int mt = 0; mt < 4; mt++) {
                uint32_t addr = as0 +
                    (uint32_t)(((wm * 64 + mt * 16 + a_row) * AS_H + k0 + a_k) * 2);
                ldm_x4(af[mt][0], af[mt][1], af[mt][2], af[mt][3], addr);
            }
            #pragma unroll
            for (int p = 0; p < 2; p++) {
                uint32_t addr = bs0 +
                    (uint32_t)(((wn * 32 + p * 16 + b_row) * AS_H + k0 + b_k) * 2);
                ldm_x4(bf[2 * p][0], bf[2 * p][1], bf[2 * p + 1][0], bf[2 * p + 1][1], addr);
            }
            #pragma unroll
            for (int mt = 0; mt < 4; mt++)
                #pragma unroll
                for (int nt = 0; nt < 4; nt++)
                    mma_f16(acc[mt][nt], af[mt], bf[nt]);
        }
    }

    #pragma unroll
    for (int mt = 0; mt < 4; mt++) {
        #pragma unroll
        for (int rr = 0; rr < 2; rr++) {
            int row = bm + wm * 64 + mt * 16 + grp + rr * 8;
            int b   = row / N_TOK;
            int n   = row - b * N_TOK;
            #pragma unroll
            for (int nt = 0; nt < 4; nt++) {
                int col0 = bn + wn * 32 + nt * 8 + (tig << 1);
                float v0 = acc[mt][nt][rr * 2 + 0] + bias[col0];
                float v1 = acc[mt][nt][rr * 2 + 1] + bias[col0 + 1];
                if (EPI == 0) {
                    int which = col0 >> 9;
                    int h     = (col0 >> 5) & 15;
                    int d     = col0 & 31;
                    __half* dst = (which == 0) ? g_q : ((which == 1) ? g_k : g_v);
                    dst += (((size_t)b * NH + h) * N_TOK + n) * HD + d;
                    *(__half2*)dst = __floats2half2_rn(v0, v1);
                } else {
                    *(float2*)&Cout[(size_t)row * N + col0] = make_float2(v0, v1);
                }
            }
        }
    }
}

// ---------------- converters ----------------
__global__ void cvt_x_kernel(const float4* __restrict__ src)
{
    size_t i = (size_t)blockIdx.x * blockDim.x + threadIdx.x;
    float4 v = src[i];
    __half2 a = __floats2half2_rn(v.x, v.y);
    __half2 b = __floats2half2_rn(v.z, v.w);
    uint2 o = make_uint2(*(uint32_t*)&a, *(uint32_t*)&b);
    ((uint2*)g_xh)[i] = o;
}

template<int W>
__global__ void transpose_cvt_kernel(const float* __restrict__ src, int K, int N)
{
    __half* dst = (W == 0) ? g_wqkvh : g_wprojh;
    __shared__ float t[32][33];
    int nx = blockIdx.x * 32, kx = blockIdx.y * 32;
    #pragma unroll
    for (int i = 0; i < 4; i++)
        t[threadIdx.y + 8 * i][threadIdx.x] =
            src[(size_t)(kx + threadIdx.y + 8 * i) * N + nx + threadIdx.x];
    __syncthreads();
    #pragma unroll
    for (int i = 0; i < 4; i++)
        dst[(size_t)(nx + threadIdx.y + 8 * i) * K + kx + threadIdx.x] =
            __float2half_rn(t[threadIdx.x][threadIdx.y + 8 * i]);
}

// ---------------- pipelined tensor-core attention ---------------------------
// One 128-thread block handles NPAIR consecutive windows at one head.
// Q/K/V double-buffered via cp.async (load pair i+1 overlaps compute pair i).
// V stored ROW-major; PV B-fragments via ldmatrix.trans.
// smem bytes: buf[2] x {hQ 64x40, hK 64x40, hV 64x40} = 30720,
//             hP 64x72 @30720 (9216), fBs @39936 (676) -> 40612 total.
#define NPAIR   8
#define BUF_B   15360          // bytes per buffer (3 * 64*40*2)
#define OFF_K   5120
#define OFF_V   10240
#define OFF_P   30720
#define OFF_BS  39936
#define AT_SMEM 40612
#define QK_ST 40               // halves per row
#define P_ST  72

__global__ __launch_bounds__(128, 4)
void attn_mma_kernel(const float* __restrict__ bias_table)
{
    const int h   = blockIdx.x;
    const int w0  = blockIdx.y * NPAIR;
    const int t   = threadIdx.x;
    const int warp = t >> 5;
    const int lane = t & 31;

    __shared__ __align__(16) char sm_raw[AT_SMEM];
    const uint32_t smb = (uint32_t)__cvta_generic_to_shared(sm_raw);
    float* fBs = (float*)(sm_raw + OFF_BS);

    // bias slice: once per block (shared by all NPAIR windows)
    for (int i = t; i < 169; i += 128) fBs[i] = bias_table[i * NH + h];

    // zero pad rows 49..63 of Q/K/V in BOTH buffers (written once; cp.async
    // only touches rows 0..48). 15 rows x 20 u32 x 3 arrays x 2 bufs = 1800.
    for (int i = t; i < 1800; i += 128) {
        int b   = i / 900;
        int rem = i - b * 900;
        int arr = rem / 300;
        int r2  = rem - arr * 300;
        int row = r2 / 20, col = r2 - (r2 / 20) * 20;
        *(uint32_t*)(sm_raw + b * BUF_B + arr * OFF_K + (49 + row) * 80 + col * 4) = 0u;
    }
    // zero hP pad cols 56..63 (constant across pairs; softmax writes 0..55)
    {
        int r = t >> 1, c = 56 + (t & 1) * 4;
        *(uint2*)(sm_raw + OFF_P + (r * P_ST + c) * 2) = make_uint2(0u, 0u);
    }

    auto load_pair = [&](int i, int buf) {
        const size_t base = ((size_t)(w0 + i) * NH + h) * (N_TOK * HD);
        const uint32_t sb = smb + buf * BUF_B;
        const __half* gq = g_q + base;
        const __half* gk = g_k + base;
        const __half* gv = g_v + base;
        #pragma unroll
        for (int f = 0; f < 2; f++) {          // 196 uint4 per array
            int idx = t + f * 128;
            if (idx < 196) {
                int n = idx >> 2, sg = idx & 3;
                uint32_t off = (uint32_t)(n * 80 + sg * 16);
                cp_async16_u(sb + off,           gq + idx * 8);
                cp_async16_u(sb + OFF_K + off,   gk + idx * 8);
                cp_async16_u(sb + OFF_V + off,   gv + idx * 8);
            }
        }
        cp_commit();
    };

    load_pair(0, 0);

    // ldmatrix lane-address components
    const int lg = lane >> 3, lr = lane & 7;
    const int a_row = (lg & 1) * 8 + lr;       // A operand (non-trans)
    const int a_k   = (lg >> 1) * 8;
    const int b_row = (lg >> 1) * 8 + lr;      // B non-trans (K)
    const int b_k   = (lg & 1) * 8;
    const int v_row = (lg & 1) * 8 + lr;       // B trans (V): role swap
    const int v_col = (lg >> 1) * 8;
    const int grp = lane >> 2, tig = lane & 3;
    const float scale = 0.04419417382415922f;  // 512^-0.5

    #pragma unroll 1
    for (int i = 0; i < NPAIR; i++) {
        cp_wait0();
        __syncthreads();                       // buf i ready; compute i-1 done
        if (i + 1 < NPAIR) load_pair(i + 1, (i + 1) & 1);

        const uint32_t sb = smb + (i & 1) * BUF_B;
        const uint32_t qb = sb, kb = sb + OFF_K, vb = sb + OFF_V;
        const uint32_t pb = smb + OFF_P;

        // ---- S = Q K^T : warp rows 16*warp..+15 ----
        float sc[7][4];
        #pragma unroll
        for (int nt = 0; nt < 7; nt++)
            #pragma unroll
            for (int r = 0; r < 4; r++) sc[nt][r] = 0.f;

        #pragma unroll
        for (int ks = 0; ks < 2; ks++) {
            const int k0 = ks * 16;
            uint32_t af[4], bf[8][2];
            ldm_x4(af[0], af[1], af[2], af[3],
                   qb + (uint32_t)(((16 * warp + a_row) * QK_ST + k0 + a_k) * 2));
            #pragma unroll
            for (int p = 0; p < 4; p++)
                ldm_x4(bf[2 * p][0], bf[2 * p][1], bf[2 * p + 1][0], bf[2 * p + 1][1],
                       kb + (uint32_t)(((p * 16 + b_row) * QK_ST + k0 + b_k) * 2));
            #pragma unroll
            for (int nt = 0; nt < 7; nt++)
                mma_f16(sc[nt], af, bf[nt]);
        }

        // ---- register softmax (quad = row; shfl over tig lanes) ----
        float inv[2];
        #pragma unroll
        for (int rr = 0; rr < 2; rr++) {
            int r  = 16 * warp + grp + 8 * rr;
            int rc = min(r, 48);
            int rd = (rc * 9363) >> 16;        // rc/7
            int rm = rc - rd * 7;
            float sv[7][2];
            float mx = -1e30f;
            #pragma unroll
            for (int nt = 0; nt < 7; nt++) {
                #pragma unroll
                for (int cc = 0; cc < 2; cc++) {
                    int m = nt * 8 + 2 * tig + cc;
                    float v = -1e30f;
                    if (m < 49) {
                        int md = (m * 9363) >> 16;
                        int mm = m - md * 7;
                        v = sc[nt][rr * 2 + cc] * scale
                          + fBs[(rd - md + 6) * 13 + (rm - mm + 6)];
                    }
                    sv[nt][cc] = v;
                    mx = fmaxf(mx, v);
                }
            }
            mx = fmaxf(mx, __shfl_xor_sync(0xffffffffu, mx, 1));
            mx = fmaxf(mx, __shfl_xor_sync(0xffffffffu, mx, 2));
            float sum = 0.f;
            #pragma unroll
            for (int nt = 0; nt < 7; nt++) {
                float e0 = fast_exp(sv[nt][0] - mx);
                float e1 = fast_exp(sv[nt][1] - mx);
                sum += e0 + e1;
                *(__half2*)(sm_raw + OFF_P + ((r * P_ST + nt * 8 + 2 * tig) * 2)) =
                    __floats2half2_rn(e0, e1);
            }
            sum += __shfl_xor_sync(0xffffffffu, sum, 1);
            sum += __shfl_xor_sync(0xffffffffu, sum, 2);
            inv[rr] = 1.f / sum;
        }
        __syncwarp();

        // ---- O = P V : A = own hP rows, B via ldmatrix.trans on row-major V
        float oc[4][4];
        #pragma unroll
        for (int nt = 0; nt < 4; nt++)
            #pragma unroll
            for (int r = 0; r < 4; r++) oc[nt][r] = 0.f;

        #pragma unroll
        for (int ks = 0; ks < 4; ks++) {
            const int k0 = ks * 16;
            uint32_t af[4], bf[4][2];
            ldm_x4(af[0], af[1], af[2], af[3],
                   pb + (uint32_t)(((16 * warp + a_row) * P_ST + k0 + a_k) * 2));
            #pragma unroll
            for (int p = 0; p < 2; p++)
                ldm_x4_t(bf[2 * p][0], bf[2 * p][1], bf[2 * p + 1][0], bf[2 * p + 1][1],
                         vb + (uint32_t)(((k0 + v_row) * QK_ST + p * 16 + v_col) * 2));
            #pragma unroll
            for (int nt = 0; nt < 4; nt++)
                mma_f16(oc[nt], af, bf[nt]);
        }

        #pragma unroll
        for (int rr = 0; rr < 2; rr++) {
            int r = 16 * warp + grp + 8 * rr;
            if (r < 49) {
                size_t rowoff = ((size_t)(w0 + i) * N_TOK + r) * CH + h * HD;
                #pragma unroll
                for (int nt = 0; nt < 4; nt++) {
                    int d = nt * 8 + 2 * tig;
                    __half2 o = __floats2half2_rn(oc[nt][rr * 2 + 0] * inv[rr],
                                                  oc[nt][rr * 2 + 1] * inv[rr]);
                    *(__half2*)(g_attn + rowoff + d) = o;
                }
            }
        }
    }
}

// ---------------- launch ----------------
extern "C" void kernel_launch(void* const* d_in, const int* in_sizes, int n_in,
                              void* d_out, int out_size)
{
    const float* x          = (const float*)d_in[0];
    const float* w_qkv      = (const float*)d_in[1];
    const float* b_qkv      = (const float*)d_in[2];
    const float* w_proj     = (const float*)d_in[3];
    const float* b_proj     = (const float*)d_in[4];
    const float* bias_table = (const float*)d_in[5];
    float* out = (float*)d_out;

    cudaFuncSetAttribute(gemm_h_kernel<0>, cudaFuncAttributeMaxDynamicSharedMemorySize, GEMM_DSM);
    cudaFuncSetAttribute(gemm_h_kernel<1>, cudaFuncAttributeMaxDynamicSharedMemorySize, GEMM_DSM);

    cvt_x_kernel<<<(M_ROWS * CH / 4) / 256, 256>>>((const float4*)x);
    transpose_cvt_kernel<0><<<dim3(QKV_N / 32, CH / 32), dim3(32, 8)>>>(w_qkv, CH, QKV_N);
    transpose_cvt_kernel<1><<<dim3(CH / 32,    CH / 32), dim3(32, 8)>>>(w_proj, CH, CH);

    gemm_h_kernel<0><<<dim3(QKV_N / 128, M_ROWS / 128), 256, GEMM_DSM>>>(b_qkv, nullptr, QKV_N);

    attn_mma_kernel<<<dim3(NH, B_WIN / NPAIR), 128>>>(bias_table);

    gemm_h_kernel<1><<<dim3(CH / 128, M_ROWS / 128), 256, GEMM_DSM>>>(b_proj, out, CH);
}

// round 14
// speedup vs baseline: 1.4137x; 1.0884x over previous
#include <cuda_runtime.h>
#include <cuda_fp16.h>
#include <cstdint>
#include <cstddef>

// ---------------- problem constants ----------------
#define B_WIN 4096
#define N_TOK 49
#define CH    512
#define NH    16
#define HD    32
#define M_ROWS (B_WIN * N_TOK)      // 200704
#define QKV_N  (3 * CH)             // 1536

// ---------------- scratch (static device globals; alloc-free rule) ----------
__device__ __half g_xh   [(long long)M_ROWS * CH];            // x in fp16
__device__ __half g_q    [(long long)B_WIN * NH * N_TOK * HD];// [B,H,N,hd] fp16
__device__ __half g_k    [(long long)B_WIN * NH * N_TOK * HD];
__device__ __half g_v    [(long long)B_WIN * NH * N_TOK * HD];
__device__ __half g_attn [(long long)M_ROWS * CH];            // [B,N,C] fp16
__device__ __half g_wqkvh[(long long)QKV_N * CH];             // [N=1536,K=512] K-major fp16
__device__ __half g_wprojh[(long long)CH * CH];               // [N=512, K=512] K-major fp16

// ---------------- PTX helpers ----------------
__device__ __forceinline__ void mma_f16(float c[4], const uint32_t a[4], const uint32_t b[2]) {
    asm volatile(
        "mma.sync.aligned.m16n8k16.row.col.f32.f16.f16.f32 "
        "{%0,%1,%2,%3}, {%4,%5,%6,%7}, {%8,%9}, {%0,%1,%2,%3};\n"
        : "+f"(c[0]), "+f"(c[1]), "+f"(c[2]), "+f"(c[3])
        : "r"(a[0]), "r"(a[1]), "r"(a[2]), "r"(a[3]),
          "r"(b[0]), "r"(b[1]));
}
__device__ __forceinline__ void ldm_x4(uint32_t& r0, uint32_t& r1, uint32_t& r2, uint32_t& r3,
                                       uint32_t saddr) {
    asm volatile("ldmatrix.sync.aligned.m8n8.x4.shared.b16 {%0,%1,%2,%3}, [%4];"
                 : "=r"(r0), "=r"(r1), "=r"(r2), "=r"(r3) : "r"(saddr));
}
__device__ __forceinline__ void ldm_x4_t(uint32_t& r0, uint32_t& r1, uint32_t& r2, uint32_t& r3,
                                         uint32_t saddr) {
    asm volatile("ldmatrix.sync.aligned.m8n8.x4.trans.shared.b16 {%0,%1,%2,%3}, [%4];"
                 : "=r"(r0), "=r"(r1), "=r"(r2), "=r"(r3) : "r"(saddr));
}
__device__ __forceinline__ void cp_async16_u(uint32_t saddr, const void* gmem) {
    asm volatile("cp.async.cg.shared.global [%0], [%1], 16;\n" :: "r"(saddr), "l"(gmem));
}
__device__ __forceinline__ void cp_commit() { asm volatile("cp.async.commit_group;\n" ::: "memory"); }
__device__ __forceinline__ void cp_wait0()  { asm volatile("cp.async.wait_group 0;\n" ::: "memory"); }
__device__ __forceinline__ void cp_wait1()  { asm volatile("cp.async.wait_group 1;\n" ::: "memory"); }

// fast exp on the FFMA pipe. Valid for x <= 0 (clamped at -80).
__device__ __forceinline__ float fast_exp(float x) {
    x = fmaxf(x, -80.0f);
    float y = x * 1.4426950408889634f;
    float t = y + 12582912.0f;                 // 1.5*2^23: round-to-nearest
    int   n = __float_as_int(t) - 0x4B400000;  // integer part
    float f = y - (t - 12582912.0f);           // f in [-0.5, 0.5]
    float p = 1.33335581e-3f;
    p = fmaf(p, f, 9.61812911e-3f);
    p = fmaf(p, f, 5.55041087e-2f);
    p = fmaf(p, f, 2.40226507e-1f);
    p = fmaf(p, f, 6.93147180e-1f);
    p = fmaf(p, f, 1.0f);
    return __int_as_float(__float_as_int(p) + (n << 23));
}

// ---------------- fp16 GEMM: BK=64, 3-stage SWIZZLED ring, one sync/iter ---
// 128x128 tile, BK=64 (4 x k16), 256 threads, 8 warps (2x4), warp tile 64x32.
// Rows are 128B (64 halves); 16B chunk c of row r lives at (c ^ (r&7)).
// Stage = A 16KB + B 16KB = 32KB; 3 stages = 96KB/CTA, 2 CTAs = 192KB/SM.
#define KT_CNT (CH / 64)             // 8
#define OPER_B 16384u                // bytes per operand per stage
#define STAGE_B (2 * OPER_B)         // 32768
#define GEMM_DSM (3 * STAGE_B)       // 98304 bytes

template<int EPI>
__global__ __launch_bounds__(256, 2)
void gemm_h_kernel(const float* __restrict__ bias, float* __restrict__ Cout, int N)
{
    extern __shared__ __half dsm[];

    const __half* A  = (EPI == 0) ? g_xh   : g_attn;
    const __half* Bt = (EPI == 0) ? g_wqkvh : g_wprojh;

    const int tid  = threadIdx.x;
    const int lane = tid & 31;
    const int warp = tid >> 5;
    const int wm   = warp >> 2;
    const int wn   = warp & 3;
    const int bm   = blockIdx.y * 128;
    const int bn   = blockIdx.x * 128;
    const int grp  = lane >> 2;
    const int tig  = lane & 3;

    const int lg  = lane >> 3;
    const int lr  = lane & 7;
    const int a_row = (lg & 1) * 8 + lr;
    const int a_c16 = (lg >> 1);               // 16B-chunk idx within k-step: 0/1
    const int b_row = (lg >> 1) * 8 + lr;
    const int b_c16 = (lg & 1);

    const uint32_t sm_base = (uint32_t)__cvta_generic_to_shared(dsm);

    float acc[4][4][4];
    #pragma unroll
    for (int mt = 0; mt < 4; mt++)
        #pragma unroll
        for (int nt = 0; nt < 4; nt++)
            #pragma unroll
            for (int r = 0; r < 4; r++) acc[mt][nt][r] = 0.0f;

    auto load_stage = [&](int kt, int s) {
        const uint32_t sA = sm_base + (uint32_t)(s * STAGE_B);
        const uint32_t sB = sA + OPER_B;
        #pragma unroll
        for (int i = 0; i < 4; i++) {
            int idx = tid + i * 256;            // 0..1023
            int row = idx >> 3, seg = idx & 7;
            uint32_t off = (uint32_t)(row * 128 + ((seg ^ (row & 7)) << 4));
            cp_async16_u(sA + off, A + (size_t)(bm + row) * CH + kt * 64 + seg * 8);
        }
        #pragma unroll
        for (int i = 0; i < 4; i++) {
            int idx = tid + i * 256;
            int row = idx >> 3, seg = idx & 7;
            uint32_t off = (uint32_t)(row * 128 + ((seg ^ (row & 7)) << 4));
            cp_async16_u(sB + off, Bt + (size_t)(bn + row) * CH + kt * 64 + seg * 8);
        }
        cp_commit();
    };

    load_stage(0, 0);
    load_stage(1, 1);

    #pragma unroll 1
    for (int kt = 0; kt < KT_CNT; kt++) {
        if (kt == KT_CNT - 1) cp_wait0(); else cp_wait1();   // stage kt done
        __syncthreads();                        // + compute kt-1 done everywhere
        if (kt + 2 < KT_CNT) load_stage(kt + 2, (kt + 2) % 3);

        const uint32_t as0 = sm_base + (uint32_t)((kt % 3) * STAGE_B);
        const uint32_t bs0 = as0 + OPER_B;
        #pragma unroll
        for (int ks = 0; ks < 4; ks++) {
            const int kc = ks * 2;              // 16B-chunk base within row
            uint32_t af[4][4], bf[4][2];
            #pragma unroll
            for (int mt = 0; mt < 4; mt++) {
                int row = wm * 64 + mt * 16 + a_row;
                uint32_t addr = as0 +
                    (uint32_t)(row * 128 + (((kc + a_c16) ^ (row & 7)) << 4));
                ldm_x4(af[mt][0], af[mt][1], af[mt][2], af[mt][3], addr);
            }
            #pragma unroll
            for (int p = 0; p < 2; p++) {
                int row = wn * 32 + p * 16 + b_row;
                uint32_t addr = bs0 +
                    (uint32_t)(row * 128 + (((kc + b_c16) ^ (row & 7)) << 4));
                ldm_x4(bf[2 * p][0], bf[2 * p][1], bf[2 * p + 1][0], bf[2 * p + 1][1], addr);
            }
            #pragma unroll
            for (int mt = 0; mt < 4; mt++)
                #pragma unroll
                for (int nt = 0; nt < 4; nt++)
                    mma_f16(acc[mt][nt], af[mt], bf[nt]);
        }
    }

    // -------- epilogue --------
    #pragma unroll
    for (int mt = 0; mt < 4; mt++) {
        #pragma unroll
        for (int rr = 0; rr < 2; rr++) {
            int row = bm + wm * 64 + mt * 16 + grp + rr * 8;
            int b   = row / N_TOK;
            int n   = row - b * N_TOK;
            #pragma unroll
            for (int nt = 0; nt < 4; nt++) {
                int col0 = bn + wn * 32 + nt * 8 + (tig << 1);
                float v0 = acc[mt][nt][rr * 2 + 0] + bias[col0];
                float v1 = acc[mt][nt][rr * 2 + 1] + bias[col0 + 1];
                if (EPI == 0) {
                    int which = col0 >> 9;
                    int h     = (col0 >> 5) & 15;
                    int d     = col0 & 31;
                    __half* dst = (which == 0) ? g_q : ((which == 1) ? g_k : g_v);
                    dst += (((size_t)b * NH + h) * N_TOK + n) * HD + d;
                    *(__half2*)dst = __floats2half2_rn(v0, v1);
                } else {
                    *(float2*)&Cout[(size_t)row * N + col0] = make_float2(v0, v1);
                }
            }
        }
    }
}

// ---------------- converters ----------------
__global__ void cvt_x_kernel(const float4* __restrict__ src)
{
    size_t i = (size_t)blockIdx.x * blockDim.x + threadIdx.x;
    float4 v = src[i];
    __half2 a = __floats2half2_rn(v.x, v.y);
    __half2 b = __floats2half2_rn(v.z, v.w);
    uint2 o = make_uint2(*(uint32_t*)&a, *(uint32_t*)&b);
    ((uint2*)g_xh)[i] = o;
}

template<int W>
__global__ void transpose_cvt_kernel(const float* __restrict__ src, int K, int N)
{
    __half* dst = (W == 0) ? g_wqkvh : g_wprojh;
    __shared__ float t[32][33];
    int nx = blockIdx.x * 32, kx = blockIdx.y * 32;
    #pragma unroll
    for (int i = 0; i < 4; i++)
        t[threadIdx.y + 8 * i][threadIdx.x] =
            src[(size_t)(kx + threadIdx.y + 8 * i) * N + nx + threadIdx.x];
    __syncthreads();
    #pragma unroll
    for (int i = 0; i < 4; i++)
        dst[(size_t)(nx + threadIdx.y + 8 * i) * K + kx + threadIdx.x] =
            __float2half_rn(t[threadIdx.x][threadIdx.y + 8 * i]);
}

// ---------------- pipelined tensor-core attention (unchanged, round 13) ----
#define NPAIR   8
#define BUF_B   15360          // bytes per buffer (3 * 64*40*2)
#define OFF_K   5120
#define OFF_V   10240
#define OFF_P   30720
#define OFF_BS  39936
#define AT_SMEM 40612
#define QK_ST 40               // halves per row
#define P_ST  72

__global__ __launch_bounds__(128, 4)
void attn_mma_kernel(const float* __restrict__ bias_table)
{
    const int h   = blockIdx.x;
    const int w0  = blockIdx.y * NPAIR;
    const int t   = threadIdx.x;
    const int warp = t >> 5;
    const int lane = t & 31;

    __shared__ __align__(16) char sm_raw[AT_SMEM];
    const uint32_t smb = (uint32_t)__cvta_generic_to_shared(sm_raw);
    float* fBs = (float*)(sm_raw + OFF_BS);

    for (int i = t; i < 169; i += 128) fBs[i] = bias_table[i * NH + h];

    for (int i = t; i < 1800; i += 128) {
        int b   = i / 900;
        int rem = i - b * 900;
        int arr = rem / 300;
        int r2  = rem - arr * 300;
        int row = r2 / 20, col = r2 - (r2 / 20) * 20;
        *(uint32_t*)(sm_raw + b * BUF_B + arr * OFF_K + (49 + row) * 80 + col * 4) = 0u;
    }
    {
        int r = t >> 1, c = 56 + (t & 1) * 4;
        *(uint2*)(sm_raw + OFF_P + (r * P_ST + c) * 2) = make_uint2(0u, 0u);
    }

    auto load_pair = [&](int i, int buf) {
        const size_t base = ((size_t)(w0 + i) * NH + h) * (N_TOK * HD);
        const uint32_t sb = smb + buf * BUF_B;
        const __half* gq = g_q + base;
        const __half* gk = g_k + base;
        const __half* gv = g_v + base;
        #pragma unroll
        for (int f = 0; f < 2; f++) {          // 196 uint4 per array
            int idx = t + f * 128;
            if (idx < 196) {
                int n = idx >> 2, sg = idx & 3;
                uint32_t off = (uint32_t)(n * 80 + sg * 16);
                cp_async16_u(sb + off,           gq + idx * 8);
                cp_async16_u(sb + OFF_K + off,   gk + idx * 8);
                cp_async16_u(sb + OFF_V + off,   gv + idx * 8);
            }
        }
        cp_commit();
    };

    load_pair(0, 0);

    const int lg = lane >> 3, lr = lane & 7;
    const int a_row = (lg & 1) * 8 + lr;
    const int a_k   = (lg >> 1) * 8;
    const int b_row = (lg >> 1) * 8 + lr;
    const int b_k   = (lg & 1) * 8;
    const int v_row = (lg & 1) * 8 + lr;
    const int v_col = (lg >> 1) * 8;
    const int grp = lane >> 2, tig = lane & 3;
    const float scale = 0.04419417382415922f;  // 512^-0.5

    #pragma unroll 1
    for (int i = 0; i < NPAIR; i++) {
        cp_wait0();
        __syncthreads();
        if (i + 1 < NPAIR) load_pair(i + 1, (i + 1) & 1);

        const uint32_t sb = smb + (i & 1) * BUF_B;
        const uint32_t qb = sb, kb = sb + OFF_K, vb = sb + OFF_V;
        const uint32_t pb = smb + OFF_P;

        float sc[7][4];
        #pragma unroll
        for (int nt = 0; nt < 7; nt++)
            #pragma unroll
            for (int r = 0; r < 4; r++) sc[nt][r] = 0.f;

        #pragma unroll
        for (int ks = 0; ks < 2; ks++) {
            const int k0 = ks * 16;
            uint32_t af[4], bf[8][2];
            ldm_x4(af[0], af[1], af[2], af[3],
                   qb + (uint32_t)(((16 * warp + a_row) * QK_ST + k0 + a_k) * 2));
            #pragma unroll
            for (int p = 0; p < 4; p++)
                ldm_x4(bf[2 * p][0], bf[2 * p][1], bf[2 * p + 1][0], bf[2 * p + 1][1],
                       kb + (uint32_t)(((p * 16 + b_row) * QK_ST + k0 + b_k) * 2));
            #pragma unroll
            for (int nt = 0; nt < 7; nt++)
                mma_f16(sc[nt], af, bf[nt]);
        }

        float inv[2];
        #pragma unroll
        for (int rr = 0; rr < 2; rr++) {
            int r  = 16 * warp + grp + 8 * rr;
            int rc = min(r, 48);
            int rd = (rc * 9363) >> 16;
            int rm = rc - rd * 7;
            float sv[7][2];
            float mx = -1e30f;
            #pragma unroll
            for (int nt = 0; nt < 7; nt++) {
                #pragma unroll
                for (int cc = 0; cc < 2; cc++) {
                    int m = nt * 8 + 2 * tig + cc;
                    float v = -1e30f;
                    if (m < 49) {
                        int md = (m * 9363) >> 16;
                        int mm = m - md * 7;
                        v = sc[nt][rr * 2 + cc] * scale
                          + fBs[(rd - md + 6) * 13 + (rm - mm + 6)];
                    }
                    sv[nt][cc] = v;
                    mx = fmaxf(mx, v);
                }
            }
            mx = fmaxf(mx, __shfl_xor_sync(0xffffffffu, mx, 1));
            mx = fmaxf(mx, __shfl_xor_sync(0xffffffffu, mx, 2));
            float sum = 0.f;
            #pragma unroll
            for (int nt = 0; nt < 7; nt++) {
                float e0 = fast_exp(sv[nt][0] - mx);
                float e1 = fast_exp(sv[nt][1] - mx);
                sum += e0 + e1;
                *(__half2*)(sm_raw + OFF_P + ((r * P_ST + nt * 8 + 2 * tig) * 2)) =
                    __floats2half2_rn(e0, e1);
            }
            sum += __shfl_xor_sync(0xffffffffu, sum, 1);
            sum += __shfl_xor_sync(0xffffffffu, sum, 2);
            inv[rr] = 1.f / sum;
        }
        __syncwarp();

        float oc[4][4];
        #pragma unroll
        for (int nt = 0; nt < 4; nt++)
            #pragma unroll
            for (int r = 0; r < 4; r++) oc[nt][r] = 0.f;

        #pragma unroll
        for (int ks = 0; ks < 4; ks++) {
            const int k0 = ks * 16;
            uint32_t af[4], bf[4][2];
            ldm_x4(af[0], af[1], af[2], af[3],
                   pb + (uint32_t)(((16 * warp + a_row) * P_ST + k0 + a_k) * 2));
            #pragma unroll
            for (int p = 0; p < 2; p++)
                ldm_x4_t(bf[2 * p][0], bf[2 * p][1], bf[2 * p + 1][0], bf[2 * p + 1][1],
                         vb + (uint32_t)(((k0 + v_row) * QK_ST + p * 16 + v_col) * 2));
            #pragma unroll
            for (int nt = 0; nt < 4; nt++)
                mma_f16(oc[nt], af, bf[nt]);
        }

        #pragma unroll
        for (int rr = 0; rr < 2; rr++) {
            int r = 16 * warp + grp + 8 * rr;
            if (r < 49) {
                size_t rowoff = ((size_t)(w0 + i) * N_TOK + r) * CH + h * HD;
                #pragma unroll
                for (int nt = 0; nt < 4; nt++) {
                    int d = nt * 8 + 2 * tig;
                    __half2 o = __floats2half2_rn(oc[nt][rr * 2 + 0] * inv[rr],
                                                  oc[nt][rr * 2 + 1] * inv[rr]);
                    *(__half2*)(g_attn + rowoff + d) = o;
                }
            }
        }
    }
}

// ---------------- launch ----------------
extern "C" void kernel_launch(void* const* d_in, const int* in_sizes, int n_in,
                              void* d_out, int out_size)
{
    const float* x          = (const float*)d_in[0];
    const float* w_qkv      = (const float*)d_in[1];
    const float* b_qkv      = (const float*)d_in[2];
    const float* w_proj     = (const float*)d_in[3];
    const float* b_proj     = (const float*)d_in[4];
    const float* bias_table = (const float*)d_in[5];
    float* out = (float*)d_out;

    cudaFuncSetAttribute(gemm_h_kernel<0>, cudaFuncAttributeMaxDynamicSharedMemorySize, GEMM_DSM);
    cudaFuncSetAttribute(gemm_h_kernel<1>, cudaFuncAttributeMaxDynamicSharedMemorySize, GEMM_DSM);

    cvt_x_kernel<<<(M_ROWS * CH / 4) / 256, 256>>>((const float4*)x);
    transpose_cvt_kernel<0><<<dim3(QKV_N / 32, CH / 32), dim3(32, 8)>>>(w_qkv, CH, QKV_N);
    transpose_cvt_kernel<1><<<dim3(CH / 32,    CH / 32), dim3(32, 8)>>>(w_proj, CH, CH);

    gemm_h_kernel<0><<<dim3(QKV_N / 128, M_ROWS / 128), 256, GEMM_DSM>>>(b_qkv, nullptr, QKV_N);

    attn_mma_kernel<<<dim3(NH, B_WIN / NPAIR), 128>>>(bias_table);

    gemm_h_kernel<1><<<dim3(CH / 128, M_ROWS / 128), 256, GEMM_DSM>>>(b_proj, out, CH);
}